// round 9
// baseline (speedup 1.0000x reference)
#include <cuda_runtime.h>
#include <cuda_bf16.h>
#include <cuda_fp16.h>
#include <cstdint>
#include <math.h>

#define BATCH 2
#define LSEQ 2048
#define DMODEL 1024
#define NHEAD 16
#define DHEAD 64
#define UTOP 40
#define MROWS (BATCH*LSEQ)          // 4096
#define BHL (BATCH*NHEAD*LSEQ)      // 65536
#define KSPLIT 8
#define KS_KEYS (LSEQ/KSPLIT)       // 256
#define MODROWS 640
#define DD (DMODEL*DMODEL)
// score gather chunking
#define NKC 8
#define KCROWS (LSEQ/NKC)           // 256 keys per chunk
#define KROWF 68                    // padded floats per smem K row
#define SCORE_SMEM (KCROWS*KROWF*4) // 69632 B

// ---------------- scratch ----------------
__device__ float g_Q[BATCH*NHEAD*LSEQ*DHEAD];
__device__ float g_K[BATCH*NHEAD*LSEQ*DHEAD];
__device__ float g_V[BATCH*NHEAD*LSEQ*DHEAD];
__device__ float g_M[BHL];
__device__ int   g_top[BATCH*NHEAD*UTOP];
__device__ float g_ctx[BATCH*NHEAD*UTOP*DHEAD];
__device__ float g_vpart[BATCH*NHEAD*KSPLIT*DHEAD];
__device__ float g_vmean[BATCH*NHEAD*DHEAD];
__device__ float g_pmc[BATCH*NHEAD*NKC*LSEQ];   // per-chunk partial max
__device__ float g_psc[BATCH*NHEAD*NKC*LSEQ];   // per-chunk partial sum
__device__ __nv_bfloat16 g_xbh[MROWS*DMODEL], g_xbl[MROWS*DMODEL];
__device__ __half        g_xfh[MROWS*DMODEL], g_xfl[MROWS*DMODEL];
__device__ __nv_bfloat16 g_wbh[2*DD], g_wbl[2*DD];   // [Wq ; Wkv_K] bf16 hi/lo
__device__ __half        g_wv[DD];                   // Wkv_V fp16
__device__ __half        g_wo[DD];                   // Wout fp16
__device__ __half        g_cmh[BATCH*MODROWS*DMODEL], g_cml[BATCH*MODROWS*DMODEL];
__device__ float g_pm[BATCH*NHEAD*UTOP*KSPLIT];
__device__ float g_ps[BATCH*NHEAD*UTOP*KSPLIT];
__device__ float g_pa[BATCH*NHEAD*UTOP*KSPLIT*DHEAD];
__device__ unsigned char g_selu[BATCH*NHEAD*LSEQ];
__device__ int   g_flags[BATCH*LSEQ];
__device__ int   g_rowlist[BATCH*MODROWS];
__device__ float g_baseout[BATCH*DMODEL];

// ================= helpers =================
#define CP_ASYNC16(dst, src) \
    asm volatile("cp.async.cg.shared.global [%0], [%1], 16;" :: "r"(dst), "l"(src))
#define CP_COMMIT() asm volatile("cp.async.commit_group;" ::: "memory")

__device__ __forceinline__ uint32_t smem_u32(const void* p) {
    uint32_t a;
    asm("{ .reg .u64 t; cvta.to.shared.u64 t, %1; cvt.u32.u64 %0, t; }" : "=r"(a) : "l"(p));
    return a;
}
__device__ __forceinline__ void mma_bf(float* c, const uint32_t* a, const uint32_t* b) {
    asm volatile("mma.sync.aligned.m16n8k16.row.col.f32.bf16.bf16.f32 "
        "{%0,%1,%2,%3}, {%4,%5,%6,%7}, {%8,%9}, {%0,%1,%2,%3};"
        : "+f"(c[0]), "+f"(c[1]), "+f"(c[2]), "+f"(c[3])
        : "r"(a[0]), "r"(a[1]), "r"(a[2]), "r"(a[3]), "r"(b[0]), "r"(b[1]));
}
__device__ __forceinline__ void mma_f16(float* c, const uint32_t* a, const uint32_t* b) {
    asm volatile("mma.sync.aligned.m16n8k16.row.col.f32.f16.f16.f32 "
        "{%0,%1,%2,%3}, {%4,%5,%6,%7}, {%8,%9}, {%0,%1,%2,%3};"
        : "+f"(c[0]), "+f"(c[1]), "+f"(c[2]), "+f"(c[3])
        : "r"(a[0]), "r"(a[1]), "r"(a[2]), "r"(a[3]), "r"(b[0]), "r"(b[1]));
}
__device__ __forceinline__ void ldsm_x4(uint32_t* r, uint32_t addr) {
    asm volatile("ldmatrix.sync.aligned.m8n8.x4.shared.b16 {%0,%1,%2,%3}, [%4];"
        : "=r"(r[0]), "=r"(r[1]), "=r"(r[2]), "=r"(r[3]) : "r"(addr));
}
// 64B rows, 4x16B blocks, XOR swizzle by row&3
__device__ __forceinline__ uint32_t sw_addr(uint32_t tile, int row, int cb) {
    return tile + (uint32_t)row * 64 + (uint32_t)((cb ^ (row & 3)) << 4);
}

// ================= conversions =================
__global__ void splitX(const float* __restrict__ src)
{
    int i = blockIdx.x * blockDim.x + threadIdx.x;
    float v = src[i];
    __nv_bfloat16 bh = __float2bfloat16(v);
    g_xbh[i] = bh;
    g_xbl[i] = __float2bfloat16(v - __bfloat162float(bh));
    __half fh = __float2half(v);
    g_xfh[i] = fh;
    g_xfl[i] = __float2half(v - __half2float(fh));
}
__global__ void splitWb(const float* __restrict__ Wq, const float* __restrict__ Wkv)
{
    int i = blockIdx.x * blockDim.x + threadIdx.x;
    float v = (i < DD) ? Wq[i] : Wkv[i - DD];
    __nv_bfloat16 h = __float2bfloat16(v);
    g_wbh[i] = h;
    g_wbl[i] = __float2bfloat16(v - __bfloat162float(h));
}
__global__ void convH(const float* __restrict__ Wkv, const float* __restrict__ Wout)
{
    int i = blockIdx.x * blockDim.x + threadIdx.x;
    if (i < DD) g_wv[i] = __float2half(Wkv[DD + i]);
    else        g_wo[i - DD] = __float2half(Wout[i - DD]);
}

// ================= tensor-core GEMM =================
// CTA tile 128x128, 8 warps 4x2, warp tile 32x64, K-chunk 32, 3-stage pipeline,
// XOR-swizzled 64B rows, ONE __syncthreads per chunk, 2 CTAs/SM.
// MODE 0: QK bf16 3-pass (N=2048), MODE 1: V fp16 2-pass, MODE 2: OUT fp16 2-pass.
#define TILEB 8192                   // 128 rows x 64B
#define NCHUNK 32
#define NSTAGE 3

template<int MODE>
__global__ void __launch_bounds__(256, 2) gemm_tc(
    const float* __restrict__ bias0, const float* __restrict__ bias1, float* __restrict__ out)
{
    constexpr int NT = (MODE == 0) ? 4 : 3;
    constexpr int STAGE = NT * TILEB;
    extern __shared__ char smem[];
    uint32_t sb = smem_u32(smem);
    const int t = threadIdx.x;
    const int wid = t >> 5;
    const int lane = t & 31;
    const int g  = lane >> 2;
    const int tg = lane & 3;
    const int wm = wid >> 1;
    const int wn = wid & 1;
    const int m0 = blockIdx.y * 128;
    const int n0 = blockIdx.x * 128;

    const char *A0, *A1, *B0, *B1 = nullptr;
    if (MODE == 0) { A0 = (const char*)g_xbh; A1 = (const char*)g_xbl;
                     B0 = (const char*)g_wbh; B1 = (const char*)g_wbl; }
    else if (MODE == 1) { A0 = (const char*)g_xfh; A1 = (const char*)g_xfl;
                          B0 = (const char*)g_wv; }
    else { A0 = (const char*)g_cmh; A1 = (const char*)g_cml;
           B0 = (const char*)g_wo; }

    const int arow = lane & 15;
    const int acb  = (lane >> 4) & 1;
    const int brow = (lane & 7) + ((lane >> 4) & 1) * 8;
    const int bcb  = (lane >> 3) & 1;

    float c[2][8][4];
    #pragma unroll
    for (int i = 0; i < 2; i++)
        #pragma unroll
        for (int j = 0; j < 8; j++)
            #pragma unroll
            for (int q = 0; q < 4; q++) c[i][j][q] = 0.f;

    auto load_chunk = [&](uint32_t stage, int kc) {
        int kb = kc * 64;
        #pragma unroll
        for (int r = 0; r < 2; r++) {
            int j   = t + r * 256;
            int row = j >> 2;
            int cb  = j & 3;
            uint32_t d = (uint32_t)row * 64 + (uint32_t)((cb ^ (row & 3)) << 4);
            int off = kb + cb * 16;
            CP_ASYNC16(stage + 0*TILEB + d, A0 + (size_t)(m0 + row) * 2048 + off);
            CP_ASYNC16(stage + 1*TILEB + d, A1 + (size_t)(m0 + row) * 2048 + off);
            CP_ASYNC16(stage + 2*TILEB + d, B0 + (size_t)(n0 + row) * 2048 + off);
            if (NT == 4)
                CP_ASYNC16(stage + 3*TILEB + d, B1 + (size_t)(n0 + row) * 2048 + off);
        }
    };

    load_chunk(sb, 0);               CP_COMMIT();
    load_chunk(sb + STAGE, 1);       CP_COMMIT();

    int stg = 0;
    for (int kc = 0; kc < NCHUNK; kc++) {
        if (kc < NCHUNK - 1) asm volatile("cp.async.wait_group 1;" ::: "memory");
        else                 asm volatile("cp.async.wait_group 0;" ::: "memory");
        __syncthreads();

        uint32_t Ah = sb + stg * STAGE + 0*TILEB;
        uint32_t Al = sb + stg * STAGE + 1*TILEB;
        uint32_t Bh = sb + stg * STAGE + 2*TILEB;
        uint32_t Bl = sb + stg * STAGE + 3*TILEB;

        #pragma unroll
        for (int ks = 0; ks < 2; ks++) {
            uint32_t ah[2][4], al[2][4];
            #pragma unroll
            for (int i = 0; i < 2; i++) {
                int row = wm * 32 + i * 16 + arow;
                int cb  = ks * 2 + acb;
                ldsm_x4(ah[i], sw_addr(Ah, row, cb));
                ldsm_x4(al[i], sw_addr(Al, row, cb));
            }
            #pragma unroll
            for (int jj = 0; jj < 4; jj++) {
                int row = wn * 64 + jj * 16 + brow;
                int cb  = ks * 2 + bcb;
                if (MODE == 0) {
                    uint32_t bh[4], bl[4];
                    ldsm_x4(bh, sw_addr(Bh, row, cb));
                    ldsm_x4(bl, sw_addr(Bl, row, cb));
                    #pragma unroll
                    for (int i = 0; i < 2; i++) {
                        mma_bf(c[i][2*jj],   ah[i], bh);
                        mma_bf(c[i][2*jj],   ah[i], bl);
                        mma_bf(c[i][2*jj],   al[i], bh);
                        mma_bf(c[i][2*jj+1], ah[i], bh + 2);
                        mma_bf(c[i][2*jj+1], ah[i], bl + 2);
                        mma_bf(c[i][2*jj+1], al[i], bh + 2);
                    }
                } else {
                    uint32_t bq[4];
                    ldsm_x4(bq, sw_addr(Bh, row, cb));
                    #pragma unroll
                    for (int i = 0; i < 2; i++) {
                        mma_f16(c[i][2*jj],   ah[i], bq);
                        mma_f16(c[i][2*jj],   al[i], bq);
                        mma_f16(c[i][2*jj+1], ah[i], bq + 2);
                        mma_f16(c[i][2*jj+1], al[i], bq + 2);
                    }
                }
            }
        }
        if (kc + 2 < NCHUNK) {
            int nstg = stg + 2; if (nstg >= NSTAGE) nstg -= NSTAGE;
            load_chunk(sb + nstg * STAGE, kc + 2);
            CP_COMMIT();
        }
        stg = (stg + 1 == NSTAGE) ? 0 : stg + 1;
    }

    // epilogue
    #pragma unroll
    for (int i = 0; i < 2; i++) {
        #pragma unroll
        for (int j = 0; j < 8; j++) {
            #pragma unroll
            for (int half = 0; half < 2; half++) {
                int m = m0 + wm * 32 + i * 16 + g + half * 8;
                int n = n0 + wn * 64 + j * 8 + 2 * tg;
                float v0 = c[i][j][half*2 + 0];
                float v1 = c[i][j][half*2 + 1];
                if (MODE == 0) {
                    int b_ = m >> 11, l = m & (LSEQ - 1);
                    int nloc = n & 1023;
                    int h = nloc >> 6, dh = nloc & 63;
                    const float* bias = (n < DMODEL) ? (bias0 + n) : (bias1 + n - DMODEL);
                    float* dst = ((n < DMODEL) ? g_Q : g_K)
                               + (((size_t)(b_ * NHEAD + h)) * LSEQ + l) * DHEAD + dh;
                    *(float2*)dst = make_float2(v0 + bias[0], v1 + bias[1]);
                } else if (MODE == 1) {
                    int b_ = m >> 11, l = m & (LSEQ - 1);
                    int h = n >> 6, dh = n & 63;
                    const float* bias = bias1 + DMODEL + n;
                    float* dst = g_V + (((size_t)(b_ * NHEAD + h)) * LSEQ + l) * DHEAD + dh;
                    *(float2*)dst = make_float2(v0 + bias[0], v1 + bias[1]);
                } else {
                    int b_ = m / MODROWS;
                    int i_ = m - b_ * MODROWS;
                    int l  = g_rowlist[b_ * MODROWS + i_];
                    *(float2*)(out + ((size_t)(b_ * LSEQ + l)) * DMODEL + n) =
                        make_float2(v0 + bias0[n], v1 + bias0[n + 1]);
                }
            }
        }
    }
}

// ================= M scores: SMEM-cached K gather =================
// grid (NKC, BH), block 256, smem = 256 K rows (padded). Warp per l; per l the
// 40 sampled indices are ballot-compacted, hits processed 4-at-a-time with
// 8 lanes per dot. Deterministic partial max/sum per (bh, chunk, l).
__global__ void __launch_bounds__(256, 2) score_chunk(const int* __restrict__ idxs)
{
    extern __shared__ float Ks[];
    int ck = blockIdx.x, bh = blockIdx.y;
    int t = threadIdx.x, lane = t & 31, w = t >> 5;

    // load K chunk (coalesced float4)
    const float4* Kg = (const float4*)(g_K + ((size_t)bh*LSEQ + ck*KCROWS)*DHEAD);
    for (int i = t; i < KCROWS*16; i += 256) {
        int row = i >> 4, c4 = i & 15;
        *(float4*)(Ks + row*KROWF + c4*4) = Kg[row*16 + c4];
    }
    __syncthreads();

    const int lonk = ck * KCROWS;
    const int grp = lane >> 3;        // 0..3
    const int d0  = lane & 7;         // 0..7

    for (int l = w; l < LSEQ; l += 8) {
        int i1 = idxs[l*UTOP + lane];                                  // u = lane (0..31)
        int i2 = (lane < 8) ? idxs[l*UTOP + 32 + lane] : 0x7FFFFFFF;   // u = 32..39
        bool a1 = ((unsigned)(i1 - lonk) < (unsigned)KCROWS);
        bool a2 = ((unsigned)(i2 - lonk) < (unsigned)KCROWS);
        unsigned b1 = __ballot_sync(0xffffffffu, a1);
        unsigned b2 = __ballot_sync(0xffffffffu, a2);
        int n1 = __popc(b1);
        int na = n1 + __popc(b2);

        const float4* qp = (const float4*)(g_Q + ((size_t)bh*LSEQ + l)*DHEAD);
        float gmax = -1e30f, gsum = 0.f;

        for (int base = 0; base < na; base += 4) {
            int j = base + grp;
            bool act = (j < na);
            int jj = act ? j : 0;
            int srcl = (jj < n1) ? (int)__fns(b1, 0, jj + 1)
                                 : (int)__fns(b2, 0, jj - n1 + 1);
            srcl &= 31;
            int v1s = __shfl_sync(0xffffffffu, i1, srcl);
            int v2s = __shfl_sync(0xffffffffu, i2, srcl);
            int row = ((jj < n1) ? v1s : v2s) - lonk;
            row = act ? row : 0;

            const float* kr = Ks + row*KROWF + d0*8;
            float4 k0 = *(const float4*)(kr);
            float4 k1 = *(const float4*)(kr + 4);
            float4 q0 = qp[d0*2];
            float4 q1 = qp[d0*2 + 1];
            float part = k0.x*q0.x + k0.y*q0.y + k0.z*q0.z + k0.w*q0.w
                       + k1.x*q1.x + k1.y*q1.y + k1.z*q1.z + k1.w*q1.w;
            part += __shfl_xor_sync(0xffffffffu, part, 1);
            part += __shfl_xor_sync(0xffffffffu, part, 2);
            part += __shfl_xor_sync(0xffffffffu, part, 4);
            if (act && d0 == 0) { gmax = fmaxf(gmax, part); gsum += part; }
        }
        // combine the 4 group leaders (lanes 0,8,16,24); others hold identities
        gmax = fmaxf(gmax, __shfl_xor_sync(0xffffffffu, gmax, 8));
        gsum +=            __shfl_xor_sync(0xffffffffu, gsum, 8);
        gmax = fmaxf(gmax, __shfl_xor_sync(0xffffffffu, gmax, 16));
        gsum +=            __shfl_xor_sync(0xffffffffu, gsum, 16);
        if (lane == 0) {
            g_pmc[((size_t)bh*NKC + ck)*LSEQ + l] = gmax;
            g_psc[((size_t)bh*NKC + ck)*LSEQ + l] = gsum;
        }
    }
}

// ================= top-U (combines chunk partials inline) =================
__global__ void topk_kernel()
{
    int bh = blockIdx.x;
    __shared__ float vals[LSEQ];
    __shared__ float wv[8];
    __shared__ int   wi[8];
    int t = threadIdx.x, lane = t & 31, wid = t >> 5;
    for (int i = t; i < LSEQ; i += 256) {
        float m = -1e30f, s = 0.f;
        #pragma unroll
        for (int c = 0; c < NKC; c++) {
            m = fmaxf(m, g_pmc[((size_t)bh*NKC + c)*LSEQ + i]);
            s += g_psc[((size_t)bh*NKC + c)*LSEQ + i];
        }
        vals[i] = m - s * (1.0f / UTOP);
    }
    __syncthreads();
    for (int it = 0; it < UTOP; it++) {
        float v = -2e30f; int bi = 0;
        int base = t * 8;
        #pragma unroll
        for (int j = 0; j < 8; j++) {
            float x = vals[base + j];
            if (x > v) { v = x; bi = base + j; }
        }
        #pragma unroll
        for (int o = 16; o; o >>= 1) {
            float ov = __shfl_xor_sync(0xffffffffu, v, o);
            int   oi = __shfl_xor_sync(0xffffffffu, bi, o);
            if (ov > v) { v = ov; bi = oi; }
        }
        if (lane == 0) { wv[wid] = v; wi[wid] = bi; }
        __syncthreads();
        if (t < 32) {
            float v2 = (t < 8) ? wv[t] : -2e30f;
            int   i2 = (t < 8) ? wi[t] : 0;
            #pragma unroll
            for (int o = 4; o; o >>= 1) {
                float ov = __shfl_xor_sync(0xffffffffu, v2, o);
                int   oi = __shfl_xor_sync(0xffffffffu, i2, o);
                if (ov > v2) { v2 = ov; i2 = oi; }
            }
            if (t == 0) { g_top[bh*UTOP + it] = i2; vals[i2] = -1e30f; }
        }
        __syncthreads();
    }
}

// ================= V mean finish =================
__global__ void vmean_fin()
{
    int bh = blockIdx.x, dh = threadIdx.x;
    float s = 0.f;
    #pragma unroll
    for (int p = 0; p < KSPLIT; p++) s += g_vpart[((size_t)bh*KSPLIT + p)*DHEAD + dh];
    g_vmean[bh*DHEAD + dh] = s * (1.0f / LSEQ);
}

// ================= flash-split attention (+ V-mean partials) =================
__global__ void attn_flash()
{
    extern __shared__ float sm[];
    float* Qt   = sm;
    float* P    = sm + UTOP*DHEAD;
    float* mrow = P + UTOP*KS_KEYS;
    float* srow = mrow + UTOP;
    int ks = blockIdx.x, bh = blockIdx.y;
    int t = threadIdx.x, lane = t & 31, wid = t >> 5;

    for (int i = t; i < UTOP*DHEAD; i += 256) {
        int u = i >> 6, d = i & 63;
        Qt[i] = g_Q[((size_t)bh*LSEQ + g_top[bh*UTOP + u])*DHEAD + d];
    }
    __syncthreads();

    int k = ks * KS_KEYS + t;
    const float4* Kr = (const float4*)(g_K + ((size_t)bh*LSEQ + k)*DHEAD);
    float S[UTOP];
    #pragma unroll
    for (int u = 0; u < UTOP; u++) S[u] = 0.f;
    #pragma unroll
    for (int c = 0; c < 16; c++) {
        float4 kv = Kr[c];
        #pragma unroll
        for (int u = 0; u < UTOP; u++) {
            float4 qv = *(const float4*)(Qt + u*DHEAD + c*4);
            S[u] += kv.x*qv.x + kv.y*qv.y + kv.z*qv.z + kv.w*qv.w;
        }
    }
    #pragma unroll
    for (int u = 0; u < UTOP; u++) P[u*KS_KEYS + t] = S[u] * 0.125f;
    __syncthreads();

    for (int i = 0; i < 5; i++) {
        int u = wid + i*8;
        float* row = P + u*KS_KEYS;
        float m = -1e30f;
        #pragma unroll
        for (int j = 0; j < 8; j++) m = fmaxf(m, row[lane + 32*j]);
        #pragma unroll
        for (int o = 16; o; o >>= 1) m = fmaxf(m, __shfl_xor_sync(0xffffffffu, m, o));
        float s = 0.f;
        #pragma unroll
        for (int j = 0; j < 8; j++) {
            float e = __expf(row[lane + 32*j] - m);
            row[lane + 32*j] = e;
            s += e;
        }
        #pragma unroll
        for (int o = 16; o; o >>= 1) s += __shfl_xor_sync(0xffffffffu, s, o);
        if (lane == 0) { mrow[u] = m; srow[u] = s; }
    }
    __syncthreads();

    int d = t & 63, ug = t >> 6;
    float acc[10];
    #pragma unroll
    for (int i = 0; i < 10; i++) acc[i] = 0.f;
    float msum = 0.f;
    const float* Vb = g_V + ((size_t)bh*LSEQ + ks*KS_KEYS)*DHEAD + d;
    for (int kc = 0; kc < KS_KEYS/4; kc++) {
        float v0 = Vb[(size_t)(kc*4+0)*DHEAD];
        float v1 = Vb[(size_t)(kc*4+1)*DHEAD];
        float v2 = Vb[(size_t)(kc*4+2)*DHEAD];
        float v3 = Vb[(size_t)(kc*4+3)*DHEAD];
        msum += v0 + v1 + v2 + v3;
        #pragma unroll
        for (int i = 0; i < 10; i++) {
            int u = ug*10 + i;
            float4 p4 = *(const float4*)(P + u*KS_KEYS + kc*4);
            acc[i] += p4.x*v0 + p4.y*v1 + p4.z*v2 + p4.w*v3;
        }
    }
    if (ug == 0)
        g_vpart[((size_t)bh*KSPLIT + ks)*DHEAD + d] = msum;
    #pragma unroll
    for (int i = 0; i < 10; i++) {
        int u = ug*10 + i;
        g_pa[(((size_t)(bh*UTOP + u))*KSPLIT + ks)*DHEAD + d] = acc[i];
    }
    if (t < UTOP) {
        g_pm[(bh*UTOP + t)*KSPLIT + ks] = mrow[t];
        g_ps[(bh*UTOP + t)*KSPLIT + ks] = srow[t];
    }
}

__global__ void attn_combine()
{
    int bhu = blockIdx.x;
    int d = threadIdx.x;
    float m = -1e30f;
    #pragma unroll
    for (int j = 0; j < KSPLIT; j++) m = fmaxf(m, g_pm[bhu*KSPLIT + j]);
    float s = 0.f, a = 0.f;
    #pragma unroll
    for (int j = 0; j < KSPLIT; j++) {
        float w = __expf(g_pm[bhu*KSPLIT + j] - m);
        s += w * g_ps[bhu*KSPLIT + j];
        a += w * g_pa[((size_t)bhu*KSPLIT + j)*DHEAD + d];
    }
    g_ctx[(size_t)bhu*DHEAD + d] = a / s;
}

// ================= output-projection compaction =================
__global__ void sel_clear()
{
    int i = blockIdx.x * blockDim.x + threadIdx.x;
    g_selu[i] = 0;
    if (i < BATCH*LSEQ) g_flags[i] = 0;
}
__global__ void sel_mark()
{
    int bh = blockIdx.x, u = threadIdx.x;
    int l = g_top[bh*UTOP + u];
    g_selu[bh*LSEQ + l] = (unsigned char)(u + 1);
    int b_ = bh / NHEAD;
    g_flags[b_*LSEQ + l] = 1;
}
__global__ void compact_kernel()
{
    int b = blockIdx.x, t = threadIdx.x;
    __shared__ int cnts[256];
    __shared__ int l0s;
    int mine[8];
    int cnt = 0;
    #pragma unroll
    for (int j = 0; j < 8; j++) {
        mine[j] = g_flags[b*LSEQ + t*8 + j];
        cnt += mine[j];
    }
    cnts[t] = cnt;
    __syncthreads();
    for (int off = 1; off < 256; off <<= 1) {
        int v = (t >= off) ? cnts[t - off] : 0;
        __syncthreads();
        cnts[t] += v;
        __syncthreads();
    }
    int pos = cnts[t] - cnt;
    int total = cnts[255];
    #pragma unroll
    for (int j = 0; j < 8; j++)
        if (mine[j]) g_rowlist[b*MODROWS + pos++] = t*8 + j;
    __syncthreads();
    if (t == 0) l0s = g_rowlist[b*MODROWS];
    __syncthreads();
    for (int i = total + t; i < MODROWS; i += 256) g_rowlist[b*MODROWS + i] = l0s;
}
__global__ void build_cmod()
{
    int idx = blockIdx.x * blockDim.x + threadIdx.x;
    int d = idx & 1023;
    int r = (idx >> 10) % MODROWS;
    int b = idx / (MODROWS * 1024);
    int l = g_rowlist[b*MODROWS + r];
    int h = d >> 6;
    int bh = b * NHEAD + h;
    unsigned char u = g_selu[bh*LSEQ + l];
    float v = u ? g_ctx[((size_t)bh*UTOP + (u-1))*DHEAD + (d & 63)]
                : g_vmean[bh*DHEAD + (d & 63)];
    __half hi = __float2half(v);
    g_cmh[idx] = hi;
    g_cml[idx] = __float2half(v - __half2float(hi));
}
__global__ void base_out_kernel(const float* __restrict__ Wout, const float* __restrict__ bout)
{
    int gid = blockIdx.x * 8 + (threadIdx.x >> 5);
    int lane = threadIdx.x & 31;
    int b = gid >> 10, n = gid & 1023;
    const float* w = Wout + (size_t)n * DMODEL;
    const float* cb = g_vmean + b * DMODEL;
    float s = 0.f;
    #pragma unroll 8
    for (int k = lane; k < DMODEL; k += 32) s += cb[k] * w[k];
    #pragma unroll
    for (int o = 16; o; o >>= 1) s += __shfl_xor_sync(0xffffffffu, s, o);
    if (lane == 0) g_baseout[b*DMODEL + n] = s + bout[n];
}
__global__ void broadcast_base(float* __restrict__ out)
{
    int idx = blockIdx.x * blockDim.x + threadIdx.x;
    int e = idx * 4;
    int b = e >> 21;
    float4 v = *(const float4*)(g_baseout + b*DMODEL + (e & 1023));
    *(float4*)(out + e) = v;
}

// -----------------------------------------------------------------------------
extern "C" void kernel_launch(void* const* d_in, const int* in_sizes, int n_in,
                              void* d_out, int out_size)
{
    const float* x    = (const float*)d_in[0];
    const float* Wq   = (const float*)d_in[1];
    const float* bq   = (const float*)d_in[2];
    const float* Wkv  = (const float*)d_in[3];
    const float* bkv  = (const float*)d_in[4];
    const float* Wout = (const float*)d_in[5];
    const float* bout = (const float*)d_in[6];
    const int*   idxs = (const int*)d_in[7];
    float* out = (float*)d_out;

    cudaFuncSetAttribute(gemm_tc<0>, cudaFuncAttributeMaxDynamicSharedMemorySize, NSTAGE*4*TILEB);
    cudaFuncSetAttribute(gemm_tc<1>, cudaFuncAttributeMaxDynamicSharedMemorySize, NSTAGE*3*TILEB);
    cudaFuncSetAttribute(gemm_tc<2>, cudaFuncAttributeMaxDynamicSharedMemorySize, NSTAGE*3*TILEB);
    cudaFuncSetAttribute(score_chunk, cudaFuncAttributeMaxDynamicSharedMemorySize, SCORE_SMEM);
    int attn_smem = (UTOP*DHEAD + UTOP*KS_KEYS + 2*UTOP) * sizeof(float);
    cudaFuncSetAttribute(attn_flash, cudaFuncAttributeMaxDynamicSharedMemorySize, attn_smem);

    // conversions
    splitX<<<MROWS*DMODEL/256, 256>>>(x);
    splitWb<<<2*DD/256, 256>>>(Wq, Wkv);
    convH<<<2*DD/256, 256>>>(Wkv, Wout);

    // QK projection (bf16 3-pass) and V projection (fp16 2-pass)
    gemm_tc<0><<<dim3(2*DMODEL/128, MROWS/128), 256, NSTAGE*4*TILEB>>>(bq, bkv, nullptr);
    gemm_tc<1><<<dim3(DMODEL/128, MROWS/128), 256, NSTAGE*3*TILEB>>>(nullptr, bkv, nullptr);
    // sparsity measure (smem-cached gather) + selection
    score_chunk<<<dim3(NKC, BATCH*NHEAD), 256, SCORE_SMEM>>>(idxs);
    topk_kernel<<<BATCH*NHEAD, 256>>>();
    // selection maps + compaction
    sel_clear<<<256, 256>>>();
    sel_mark<<<BATCH*NHEAD, UTOP>>>();
    compact_kernel<<<BATCH, 256>>>();
    // flash-split attention (also emits V-mean partials)
    attn_flash<<<dim3(KSPLIT, BATCH*NHEAD), 256, attn_smem>>>();
    vmean_fin<<<BATCH*NHEAD, 64>>>();
    attn_combine<<<BATCH*NHEAD*UTOP, 64>>>();
    // base output rows (exact fp32) + broadcast
    base_out_kernel<<<BATCH*DMODEL/8, 256>>>(Wout, bout);
    broadcast_base<<<MROWS*DMODEL/1024, 256>>>(out);
    // modified context rows -> fp16 split -> scatter GEMM
    build_cmod<<<BATCH*MODROWS*DMODEL/256, 256>>>();
    gemm_tc<2><<<dim3(DMODEL/128, BATCH*MODROWS/128), 256, NSTAGE*3*TILEB>>>(bout, nullptr, out);
}

// round 10
// speedup vs baseline: 1.4770x; 1.4770x over previous
#include <cuda_runtime.h>
#include <cuda_bf16.h>
#include <cuda_fp16.h>
#include <cstdint>
#include <math.h>

#define BATCH 2
#define LSEQ 2048
#define DMODEL 1024
#define NHEAD 16
#define DHEAD 64
#define UTOP 40
#define MROWS (BATCH*LSEQ)          // 4096
#define BHL (BATCH*NHEAD*LSEQ)      // 65536
#define KSPLIT 8
#define KS_KEYS (LSEQ/KSPLIT)       // 256
#define MODROWS 640
#define DD (DMODEL*DMODEL)

// ---------------- scratch ----------------
__device__ float g_Q[BATCH*NHEAD*LSEQ*DHEAD];
__device__ float g_K[BATCH*NHEAD*LSEQ*DHEAD];
__device__ float g_V[BATCH*NHEAD*LSEQ*DHEAD];
__device__ float g_M[BHL];
__device__ int   g_top[BATCH*NHEAD*UTOP];
__device__ float g_ctx[BATCH*NHEAD*UTOP*DHEAD];
__device__ float g_vpart[BATCH*NHEAD*KSPLIT*DHEAD];
__device__ float g_vmean[BATCH*NHEAD*DHEAD];
__device__ __nv_bfloat16 g_xbh[MROWS*DMODEL], g_xbl[MROWS*DMODEL];
__device__ __half        g_xfh[MROWS*DMODEL], g_xfl[MROWS*DMODEL];
__device__ __nv_bfloat16 g_wbh[2*DD], g_wbl[2*DD];   // [Wq ; Wkv_K] bf16 hi/lo
__device__ __half        g_wv[DD];                   // Wkv_V fp16
__device__ __half        g_wo[DD];                   // Wout fp16
__device__ __half        g_cmh[BATCH*MODROWS*DMODEL], g_cml[BATCH*MODROWS*DMODEL];
__device__ float g_pm[BATCH*NHEAD*UTOP*KSPLIT];
__device__ float g_ps[BATCH*NHEAD*UTOP*KSPLIT];
__device__ float g_pa[BATCH*NHEAD*UTOP*KSPLIT*DHEAD];
__device__ unsigned char g_selu[BATCH*NHEAD*LSEQ];
__device__ int   g_flags[BATCH*LSEQ];
__device__ int   g_rowlist[BATCH*MODROWS];
__device__ float g_baseout[BATCH*DMODEL];

// ================= helpers =================
#define CP_ASYNC16(dst, src) \
    asm volatile("cp.async.cg.shared.global [%0], [%1], 16;" :: "r"(dst), "l"(src))
#define CP_COMMIT() asm volatile("cp.async.commit_group;" ::: "memory")

__device__ __forceinline__ uint32_t smem_u32(const void* p) {
    uint32_t a;
    asm("{ .reg .u64 t; cvta.to.shared.u64 t, %1; cvt.u32.u64 %0, t; }" : "=r"(a) : "l"(p));
    return a;
}
__device__ __forceinline__ void mma_bf(float* c, const uint32_t* a, const uint32_t* b) {
    asm volatile("mma.sync.aligned.m16n8k16.row.col.f32.bf16.bf16.f32 "
        "{%0,%1,%2,%3}, {%4,%5,%6,%7}, {%8,%9}, {%0,%1,%2,%3};"
        : "+f"(c[0]), "+f"(c[1]), "+f"(c[2]), "+f"(c[3])
        : "r"(a[0]), "r"(a[1]), "r"(a[2]), "r"(a[3]), "r"(b[0]), "r"(b[1]));
}
__device__ __forceinline__ void mma_f16(float* c, const uint32_t* a, const uint32_t* b) {
    asm volatile("mma.sync.aligned.m16n8k16.row.col.f32.f16.f16.f32 "
        "{%0,%1,%2,%3}, {%4,%5,%6,%7}, {%8,%9}, {%0,%1,%2,%3};"
        : "+f"(c[0]), "+f"(c[1]), "+f"(c[2]), "+f"(c[3])
        : "r"(a[0]), "r"(a[1]), "r"(a[2]), "r"(a[3]), "r"(b[0]), "r"(b[1]));
}
__device__ __forceinline__ void ldsm_x4(uint32_t* r, uint32_t addr) {
    asm volatile("ldmatrix.sync.aligned.m8n8.x4.shared.b16 {%0,%1,%2,%3}, [%4];"
        : "=r"(r[0]), "=r"(r[1]), "=r"(r[2]), "=r"(r[3]) : "r"(addr));
}
// 64B rows, 4x16B blocks, XOR swizzle by row&3
__device__ __forceinline__ uint32_t sw_addr(uint32_t tile, int row, int cb) {
    return tile + (uint32_t)row * 64 + (uint32_t)((cb ^ (row & 3)) << 4);
}

// ================= conversions =================
__global__ void splitX(const float* __restrict__ src)
{
    int i = blockIdx.x * blockDim.x + threadIdx.x;
    float v = src[i];
    __nv_bfloat16 bh = __float2bfloat16(v);
    g_xbh[i] = bh;
    g_xbl[i] = __float2bfloat16(v - __bfloat162float(bh));
    __half fh = __float2half(v);
    g_xfh[i] = fh;
    g_xfl[i] = __float2half(v - __half2float(fh));
}
__global__ void splitWb(const float* __restrict__ Wq, const float* __restrict__ Wkv)
{
    int i = blockIdx.x * blockDim.x + threadIdx.x;
    float v = (i < DD) ? Wq[i] : Wkv[i - DD];
    __nv_bfloat16 h = __float2bfloat16(v);
    g_wbh[i] = h;
    g_wbl[i] = __float2bfloat16(v - __bfloat162float(h));
}
__global__ void convH(const float* __restrict__ Wkv, const float* __restrict__ Wout)
{
    int i = blockIdx.x * blockDim.x + threadIdx.x;
    if (i < DD) g_wv[i] = __float2half(Wkv[DD + i]);
    else        g_wo[i - DD] = __float2half(Wout[i - DD]);
}

// ================= tensor-core GEMM =================
// CTA tile 128x128, 8 warps 4x2, warp tile 32x64, K-chunk 32, 3-stage pipeline,
// XOR-swizzled 64B rows, ONE __syncthreads per chunk, 2 CTAs/SM.
// MODE 0: QK bf16 3-pass (N=2048), MODE 1: V fp16 2-pass, MODE 2: OUT fp16 2-pass.
#define TILEB 8192                   // 128 rows x 64B
#define NCHUNK 32
#define NSTAGE 3

template<int MODE>
__global__ void __launch_bounds__(256, 2) gemm_tc(
    const float* __restrict__ bias0, const float* __restrict__ bias1, float* __restrict__ out)
{
    constexpr int NT = (MODE == 0) ? 4 : 3;
    constexpr int STAGE = NT * TILEB;
    extern __shared__ char smem[];
    uint32_t sb = smem_u32(smem);
    const int t = threadIdx.x;
    const int wid = t >> 5;
    const int lane = t & 31;
    const int g  = lane >> 2;
    const int tg = lane & 3;
    const int wm = wid >> 1;
    const int wn = wid & 1;
    const int m0 = blockIdx.y * 128;
    const int n0 = blockIdx.x * 128;

    const char *A0, *A1, *B0, *B1 = nullptr;
    if (MODE == 0) { A0 = (const char*)g_xbh; A1 = (const char*)g_xbl;
                     B0 = (const char*)g_wbh; B1 = (const char*)g_wbl; }
    else if (MODE == 1) { A0 = (const char*)g_xfh; A1 = (const char*)g_xfl;
                          B0 = (const char*)g_wv; }
    else { A0 = (const char*)g_cmh; A1 = (const char*)g_cml;
           B0 = (const char*)g_wo; }

    const int arow = lane & 15;
    const int acb  = (lane >> 4) & 1;
    const int brow = (lane & 7) + ((lane >> 4) & 1) * 8;
    const int bcb  = (lane >> 3) & 1;

    float c[2][8][4];
    #pragma unroll
    for (int i = 0; i < 2; i++)
        #pragma unroll
        for (int j = 0; j < 8; j++)
            #pragma unroll
            for (int q = 0; q < 4; q++) c[i][j][q] = 0.f;

    auto load_chunk = [&](uint32_t stage, int kc) {
        int kb = kc * 64;
        #pragma unroll
        for (int r = 0; r < 2; r++) {
            int j   = t + r * 256;
            int row = j >> 2;
            int cb  = j & 3;
            uint32_t d = (uint32_t)row * 64 + (uint32_t)((cb ^ (row & 3)) << 4);
            int off = kb + cb * 16;
            CP_ASYNC16(stage + 0*TILEB + d, A0 + (size_t)(m0 + row) * 2048 + off);
            CP_ASYNC16(stage + 1*TILEB + d, A1 + (size_t)(m0 + row) * 2048 + off);
            CP_ASYNC16(stage + 2*TILEB + d, B0 + (size_t)(n0 + row) * 2048 + off);
            if (NT == 4)
                CP_ASYNC16(stage + 3*TILEB + d, B1 + (size_t)(n0 + row) * 2048 + off);
        }
    };

    load_chunk(sb, 0);               CP_COMMIT();
    load_chunk(sb + STAGE, 1);       CP_COMMIT();

    int stg = 0;
    for (int kc = 0; kc < NCHUNK; kc++) {
        if (kc < NCHUNK - 1) asm volatile("cp.async.wait_group 1;" ::: "memory");
        else                 asm volatile("cp.async.wait_group 0;" ::: "memory");
        __syncthreads();

        uint32_t Ah = sb + stg * STAGE + 0*TILEB;
        uint32_t Al = sb + stg * STAGE + 1*TILEB;
        uint32_t Bh = sb + stg * STAGE + 2*TILEB;
        uint32_t Bl = sb + stg * STAGE + 3*TILEB;

        #pragma unroll
        for (int ks = 0; ks < 2; ks++) {
            uint32_t ah[2][4], al[2][4];
            #pragma unroll
            for (int i = 0; i < 2; i++) {
                int row = wm * 32 + i * 16 + arow;
                int cb  = ks * 2 + acb;
                ldsm_x4(ah[i], sw_addr(Ah, row, cb));
                ldsm_x4(al[i], sw_addr(Al, row, cb));
            }
            #pragma unroll
            for (int jj = 0; jj < 4; jj++) {
                int row = wn * 64 + jj * 16 + brow;
                int cb  = ks * 2 + bcb;
                if (MODE == 0) {
                    uint32_t bh[4], bl[4];
                    ldsm_x4(bh, sw_addr(Bh, row, cb));
                    ldsm_x4(bl, sw_addr(Bl, row, cb));
                    #pragma unroll
                    for (int i = 0; i < 2; i++) {
                        mma_bf(c[i][2*jj],   ah[i], bh);
                        mma_bf(c[i][2*jj],   ah[i], bl);
                        mma_bf(c[i][2*jj],   al[i], bh);
                        mma_bf(c[i][2*jj+1], ah[i], bh + 2);
                        mma_bf(c[i][2*jj+1], ah[i], bl + 2);
                        mma_bf(c[i][2*jj+1], al[i], bh + 2);
                    }
                } else {
                    uint32_t bq[4];
                    ldsm_x4(bq, sw_addr(Bh, row, cb));
                    #pragma unroll
                    for (int i = 0; i < 2; i++) {
                        mma_f16(c[i][2*jj],   ah[i], bq);
                        mma_f16(c[i][2*jj],   al[i], bq);
                        mma_f16(c[i][2*jj+1], ah[i], bq + 2);
                        mma_f16(c[i][2*jj+1], al[i], bq + 2);
                    }
                }
            }
        }
        if (kc + 2 < NCHUNK) {
            int nstg = stg + 2; if (nstg >= NSTAGE) nstg -= NSTAGE;
            load_chunk(sb + nstg * STAGE, kc + 2);
            CP_COMMIT();
        }
        stg = (stg + 1 == NSTAGE) ? 0 : stg + 1;
    }

    // epilogue
    #pragma unroll
    for (int i = 0; i < 2; i++) {
        #pragma unroll
        for (int j = 0; j < 8; j++) {
            #pragma unroll
            for (int half = 0; half < 2; half++) {
                int m = m0 + wm * 32 + i * 16 + g + half * 8;
                int n = n0 + wn * 64 + j * 8 + 2 * tg;
                float v0 = c[i][j][half*2 + 0];
                float v1 = c[i][j][half*2 + 1];
                if (MODE == 0) {
                    int b_ = m >> 11, l = m & (LSEQ - 1);
                    int nloc = n & 1023;
                    int h = nloc >> 6, dh = nloc & 63;
                    const float* bias = (n < DMODEL) ? (bias0 + n) : (bias1 + n - DMODEL);
                    float* dst = ((n < DMODEL) ? g_Q : g_K)
                               + (((size_t)(b_ * NHEAD + h)) * LSEQ + l) * DHEAD + dh;
                    *(float2*)dst = make_float2(v0 + bias[0], v1 + bias[1]);
                } else if (MODE == 1) {
                    int b_ = m >> 11, l = m & (LSEQ - 1);
                    int h = n >> 6, dh = n & 63;
                    const float* bias = bias1 + DMODEL + n;
                    float* dst = g_V + (((size_t)(b_ * NHEAD + h)) * LSEQ + l) * DHEAD + dh;
                    *(float2*)dst = make_float2(v0 + bias[0], v1 + bias[1]);
                } else {
                    int b_ = m / MODROWS;
                    int i_ = m - b_ * MODROWS;
                    int l  = g_rowlist[b_ * MODROWS + i_];
                    *(float2*)(out + ((size_t)(b_ * LSEQ + l)) * DMODEL + n) =
                        make_float2(v0 + bias0[n], v1 + bias0[n + 1]);
                }
            }
        }
    }
}

// ================= M scores (fp32, 2 queries per warp for ILP) =================
// Identical per-l math order to the R8 kernel -> bitwise-identical g_M.
__global__ void score_m_kernel(const int* __restrict__ idxs)
{
    int warp = (blockIdx.x * blockDim.x + threadIdx.x) >> 5;   // 0 .. BHL/2-1
    int lane = threadIdx.x & 31;
    int bh = warp / (LSEQ/2);
    int l0 = (warp % (LSEQ/2)) * 2;
    const float* qr = g_Q + ((size_t)bh*LSEQ + l0) * DHEAD;
    float qa0 = qr[lane],         qa1 = qr[lane + 32];
    float qb0 = qr[DHEAD + lane], qb1 = qr[DHEAD + lane + 32];
    float mxa = -1e30f, sma = 0.f;
    float mxb = -1e30f, smb = 0.f;
    const float* Kb = g_K + (size_t)bh*LSEQ*DHEAD;
    #pragma unroll 4
    for (int u = 0; u < UTOP; u++) {
        int kia = idxs[l0*UTOP + u];
        int kib = idxs[(l0+1)*UTOP + u];
        const float* kra = Kb + (size_t)kia*DHEAD;
        const float* krb = Kb + (size_t)kib*DHEAD;
        float sa = qa0*kra[lane] + qa1*kra[lane + 32];
        float sb = qb0*krb[lane] + qb1*krb[lane + 32];
        #pragma unroll
        for (int o = 16; o; o >>= 1) {
            sa += __shfl_xor_sync(0xffffffffu, sa, o);
            sb += __shfl_xor_sync(0xffffffffu, sb, o);
        }
        mxa = fmaxf(mxa, sa); sma += sa;
        mxb = fmaxf(mxb, sb); smb += sb;
    }
    if (lane == 0) {
        g_M[(size_t)bh*LSEQ + l0]     = mxa - sma * (1.0f / UTOP);
        g_M[(size_t)bh*LSEQ + l0 + 1] = mxb - smb * (1.0f / UTOP);
    }
}

// ================= top-U =================
__global__ void topk_kernel()
{
    int bh = blockIdx.x;
    __shared__ float vals[LSEQ];
    __shared__ float wv[8];
    __shared__ int   wi[8];
    int t = threadIdx.x, lane = t & 31, wid = t >> 5;
    for (int i = t; i < LSEQ; i += 256) vals[i] = g_M[(size_t)bh*LSEQ + i];
    __syncthreads();
    for (int it = 0; it < UTOP; it++) {
        float v = -2e30f; int bi = 0;
        int base = t * 8;
        #pragma unroll
        for (int j = 0; j < 8; j++) {
            float x = vals[base + j];
            if (x > v) { v = x; bi = base + j; }
        }
        #pragma unroll
        for (int o = 16; o; o >>= 1) {
            float ov = __shfl_xor_sync(0xffffffffu, v, o);
            int   oi = __shfl_xor_sync(0xffffffffu, bi, o);
            if (ov > v) { v = ov; bi = oi; }
        }
        if (lane == 0) { wv[wid] = v; wi[wid] = bi; }
        __syncthreads();
        if (t < 32) {
            float v2 = (t < 8) ? wv[t] : -2e30f;
            int   i2 = (t < 8) ? wi[t] : 0;
            #pragma unroll
            for (int o = 4; o; o >>= 1) {
                float ov = __shfl_xor_sync(0xffffffffu, v2, o);
                int   oi = __shfl_xor_sync(0xffffffffu, i2, o);
                if (ov > v2) { v2 = ov; i2 = oi; }
            }
            if (t == 0) { g_top[bh*UTOP + it] = i2; vals[i2] = -1e30f; }
        }
        __syncthreads();
    }
}

// ================= V mean finish =================
__global__ void vmean_fin()
{
    int bh = blockIdx.x, dh = threadIdx.x;
    float s = 0.f;
    #pragma unroll
    for (int p = 0; p < KSPLIT; p++) s += g_vpart[((size_t)bh*KSPLIT + p)*DHEAD + dh];
    g_vmean[bh*DHEAD + dh] = s * (1.0f / LSEQ);
}

// ================= flash-split attention (+ V-mean partials) =================
__global__ void attn_flash()
{
    extern __shared__ float sm[];
    float* Qt   = sm;
    float* P    = sm + UTOP*DHEAD;
    float* mrow = P + UTOP*KS_KEYS;
    float* srow = mrow + UTOP;
    int ks = blockIdx.x, bh = blockIdx.y;
    int t = threadIdx.x, lane = t & 31, wid = t >> 5;

    for (int i = t; i < UTOP*DHEAD; i += 256) {
        int u = i >> 6, d = i & 63;
        Qt[i] = g_Q[((size_t)bh*LSEQ + g_top[bh*UTOP + u])*DHEAD + d];
    }
    __syncthreads();

    int k = ks * KS_KEYS + t;
    const float4* Kr = (const float4*)(g_K + ((size_t)bh*LSEQ + k)*DHEAD);
    float S[UTOP];
    #pragma unroll
    for (int u = 0; u < UTOP; u++) S[u] = 0.f;
    #pragma unroll
    for (int c = 0; c < 16; c++) {
        float4 kv = Kr[c];
        #pragma unroll
        for (int u = 0; u < UTOP; u++) {
            float4 qv = *(const float4*)(Qt + u*DHEAD + c*4);
            S[u] += kv.x*qv.x + kv.y*qv.y + kv.z*qv.z + kv.w*qv.w;
        }
    }
    #pragma unroll
    for (int u = 0; u < UTOP; u++) P[u*KS_KEYS + t] = S[u] * 0.125f;
    __syncthreads();

    for (int i = 0; i < 5; i++) {
        int u = wid + i*8;
        float* row = P + u*KS_KEYS;
        float m = -1e30f;
        #pragma unroll
        for (int j = 0; j < 8; j++) m = fmaxf(m, row[lane + 32*j]);
        #pragma unroll
        for (int o = 16; o; o >>= 1) m = fmaxf(m, __shfl_xor_sync(0xffffffffu, m, o));
        float s = 0.f;
        #pragma unroll
        for (int j = 0; j < 8; j++) {
            float e = __expf(row[lane + 32*j] - m);
            row[lane + 32*j] = e;
            s += e;
        }
        #pragma unroll
        for (int o = 16; o; o >>= 1) s += __shfl_xor_sync(0xffffffffu, s, o);
        if (lane == 0) { mrow[u] = m; srow[u] = s; }
    }
    __syncthreads();

    int d = t & 63, ug = t >> 6;
    float acc[10];
    #pragma unroll
    for (int i = 0; i < 10; i++) acc[i] = 0.f;
    float msum = 0.f;
    const float* Vb = g_V + ((size_t)bh*LSEQ + ks*KS_KEYS)*DHEAD + d;
    for (int kc = 0; kc < KS_KEYS/4; kc++) {
        float v0 = Vb[(size_t)(kc*4+0)*DHEAD];
        float v1 = Vb[(size_t)(kc*4+1)*DHEAD];
        float v2 = Vb[(size_t)(kc*4+2)*DHEAD];
        float v3 = Vb[(size_t)(kc*4+3)*DHEAD];
        msum += v0 + v1 + v2 + v3;
        #pragma unroll
        for (int i = 0; i < 10; i++) {
            int u = ug*10 + i;
            float4 p4 = *(const float4*)(P + u*KS_KEYS + kc*4);
            acc[i] += p4.x*v0 + p4.y*v1 + p4.z*v2 + p4.w*v3;
        }
    }
    if (ug == 0)
        g_vpart[((size_t)bh*KSPLIT + ks)*DHEAD + d] = msum;
    #pragma unroll
    for (int i = 0; i < 10; i++) {
        int u = ug*10 + i;
        g_pa[(((size_t)(bh*UTOP + u))*KSPLIT + ks)*DHEAD + d] = acc[i];
    }
    if (t < UTOP) {
        g_pm[(bh*UTOP + t)*KSPLIT + ks] = mrow[t];
        g_ps[(bh*UTOP + t)*KSPLIT + ks] = srow[t];
    }
}

__global__ void attn_combine()
{
    int bhu = blockIdx.x;
    int d = threadIdx.x;
    float m = -1e30f;
    #pragma unroll
    for (int j = 0; j < KSPLIT; j++) m = fmaxf(m, g_pm[bhu*KSPLIT + j]);
    float s = 0.f, a = 0.f;
    #pragma unroll
    for (int j = 0; j < KSPLIT; j++) {
        float w = __expf(g_pm[bhu*KSPLIT + j] - m);
        s += w * g_ps[bhu*KSPLIT + j];
        a += w * g_pa[((size_t)bhu*KSPLIT + j)*DHEAD + d];
    }
    g_ctx[(size_t)bhu*DHEAD + d] = a / s;
}

// ================= output-projection compaction =================
__global__ void sel_clear()
{
    int i = blockIdx.x * blockDim.x + threadIdx.x;
    g_selu[i] = 0;
    if (i < BATCH*LSEQ) g_flags[i] = 0;
}
__global__ void sel_mark()
{
    int bh = blockIdx.x, u = threadIdx.x;
    int l = g_top[bh*UTOP + u];
    g_selu[bh*LSEQ + l] = (unsigned char)(u + 1);
    int b_ = bh / NHEAD;
    g_flags[b_*LSEQ + l] = 1;
}
__global__ void compact_kernel()
{
    int b = blockIdx.x, t = threadIdx.x;
    __shared__ int cnts[256];
    __shared__ int l0s;
    int mine[8];
    int cnt = 0;
    #pragma unroll
    for (int j = 0; j < 8; j++) {
        mine[j] = g_flags[b*LSEQ + t*8 + j];
        cnt += mine[j];
    }
    cnts[t] = cnt;
    __syncthreads();
    for (int off = 1; off < 256; off <<= 1) {
        int v = (t >= off) ? cnts[t - off] : 0;
        __syncthreads();
        cnts[t] += v;
        __syncthreads();
    }
    int pos = cnts[t] - cnt;
    int total = cnts[255];
    #pragma unroll
    for (int j = 0; j < 8; j++)
        if (mine[j]) g_rowlist[b*MODROWS + pos++] = t*8 + j;
    __syncthreads();
    if (t == 0) l0s = g_rowlist[b*MODROWS];
    __syncthreads();
    for (int i = total + t; i < MODROWS; i += 256) g_rowlist[b*MODROWS + i] = l0s;
}
__global__ void build_cmod()
{
    int idx = blockIdx.x * blockDim.x + threadIdx.x;
    int d = idx & 1023;
    int r = (idx >> 10) % MODROWS;
    int b = idx / (MODROWS * 1024);
    int l = g_rowlist[b*MODROWS + r];
    int h = d >> 6;
    int bh = b * NHEAD + h;
    unsigned char u = g_selu[bh*LSEQ + l];
    float v = u ? g_ctx[((size_t)bh*UTOP + (u-1))*DHEAD + (d & 63)]
                : g_vmean[bh*DHEAD + (d & 63)];
    __half hi = __float2half(v);
    g_cmh[idx] = hi;
    g_cml[idx] = __float2half(v - __half2float(hi));
}
__global__ void base_out_kernel(const float* __restrict__ Wout, const float* __restrict__ bout)
{
    int gid = blockIdx.x * 8 + (threadIdx.x >> 5);
    int lane = threadIdx.x & 31;
    int b = gid >> 10, n = gid & 1023;
    const float* w = Wout + (size_t)n * DMODEL;
    const float* cb = g_vmean + b * DMODEL;
    float s = 0.f;
    #pragma unroll 8
    for (int k = lane; k < DMODEL; k += 32) s += cb[k] * w[k];
    #pragma unroll
    for (int o = 16; o; o >>= 1) s += __shfl_xor_sync(0xffffffffu, s, o);
    if (lane == 0) g_baseout[b*DMODEL + n] = s + bout[n];
}
__global__ void broadcast_base(float* __restrict__ out)
{
    int idx = blockIdx.x * blockDim.x + threadIdx.x;
    int e = idx * 4;
    int b = e >> 21;
    float4 v = *(const float4*)(g_baseout + b*DMODEL + (e & 1023));
    *(float4*)(out + e) = v;
}

// -----------------------------------------------------------------------------
extern "C" void kernel_launch(void* const* d_in, const int* in_sizes, int n_in,
                              void* d_out, int out_size)
{
    const float* x    = (const float*)d_in[0];
    const float* Wq   = (const float*)d_in[1];
    const float* bq   = (const float*)d_in[2];
    const float* Wkv  = (const float*)d_in[3];
    const float* bkv  = (const float*)d_in[4];
    const float* Wout = (const float*)d_in[5];
    const float* bout = (const float*)d_in[6];
    const int*   idxs = (const int*)d_in[7];
    float* out = (float*)d_out;

    cudaFuncSetAttribute(gemm_tc<0>, cudaFuncAttributeMaxDynamicSharedMemorySize, NSTAGE*4*TILEB);
    cudaFuncSetAttribute(gemm_tc<1>, cudaFuncAttributeMaxDynamicSharedMemorySize, NSTAGE*3*TILEB);
    cudaFuncSetAttribute(gemm_tc<2>, cudaFuncAttributeMaxDynamicSharedMemorySize, NSTAGE*3*TILEB);
    int attn_smem = (UTOP*DHEAD + UTOP*KS_KEYS + 2*UTOP) * sizeof(float);
    cudaFuncSetAttribute(attn_flash, cudaFuncAttributeMaxDynamicSharedMemorySize, attn_smem);

    // conversions
    splitX<<<MROWS*DMODEL/256, 256>>>(x);
    splitWb<<<2*DD/256, 256>>>(Wq, Wkv);
    convH<<<2*DD/256, 256>>>(Wkv, Wout);

    // QK projection (bf16 3-pass) and V projection (fp16 2-pass)
    gemm_tc<0><<<dim3(2*DMODEL/128, MROWS/128), 256, NSTAGE*4*TILEB>>>(bq, bkv, nullptr);
    gemm_tc<1><<<dim3(DMODEL/128, MROWS/128), 256, NSTAGE*3*TILEB>>>(nullptr, bkv, nullptr);
    // sparsity measure + selection (fp32, 2 l per warp)
    score_m_kernel<<<BHL/16, 256>>>(idxs);
    topk_kernel<<<BATCH*NHEAD, 256>>>();
    // selection maps + compaction
    sel_clear<<<256, 256>>>();
    sel_mark<<<BATCH*NHEAD, UTOP>>>();
    compact_kernel<<<BATCH, 256>>>();
    // flash-split attention (also emits V-mean partials)
    attn_flash<<<dim3(KSPLIT, BATCH*NHEAD), 256, attn_smem>>>();
    vmean_fin<<<BATCH*NHEAD, 64>>>();
    attn_combine<<<BATCH*NHEAD*UTOP, 64>>>();
    // base output rows (exact fp32) + broadcast
    base_out_kernel<<<BATCH*DMODEL/8, 256>>>(Wout, bout);
    broadcast_base<<<MROWS*DMODEL/1024, 256>>>(out);
    // modified context rows -> fp16 split -> scatter GEMM
    build_cmod<<<BATCH*MODROWS*DMODEL/256, 256>>>();
    gemm_tc<2><<<dim3(DMODEL/128, BATCH*MODROWS/128), 256, NSTAGE*3*TILEB>>>(bout, nullptr, out);
}